// round 4
// baseline (speedup 1.0000x reference)
#include <cuda_runtime.h>
#include <cstdint>
#include <math.h>

#define BB 32
#define SS 2048
#define HH 256
#define GG 1024                       // 4*H
#define BSH ((size_t)BB*SS*HH)        // hidden_seq elements

// 256 MB scratch: xg[B][S][4H], gate order f,i,c,o
__device__ float g_xg[(size_t)BB * SS * GG];

// ---------------------------------------------------------------------------
// Kernel 1: xg = x @ [Wf|Wi|Wc|Wo] + bias.  M=65536,K=256,N=1024.
// 128x128 CTA tile, 256 threads, 8x8 microtile.
// ---------------------------------------------------------------------------
__global__ __launch_bounds__(256) void xg_gemm_kernel(
    const float* __restrict__ x,
    const float* __restrict__ Wf, const float* __restrict__ Wi,
    const float* __restrict__ Wc, const float* __restrict__ Wo,
    const float* __restrict__ bf, const float* __restrict__ bi,
    const float* __restrict__ bc, const float* __restrict__ bo)
{
    __shared__ float As[32][132];     // A^T tile [k][m]
    __shared__ float Bs[32][128];     // B tile [k][n]

    const int nt = blockIdx.x & 7;
    const int m0 = (blockIdx.x >> 3) * 128;
    const int n0 = nt * 128;
    const int gate = n0 >> 8;         // tile fully inside one gate
    const float* Wg = (gate==0)?Wf:(gate==1)?Wi:(gate==2)?Wc:Wo;
    const float* bg = (gate==0)?bf:(gate==1)?bi:(gate==2)?bc:bo;
    const int j0p = n0 & 255;

    const int tid = threadIdx.x;
    const int tx = tid & 15, ty = tid >> 4;

    float acc[8][8];
    #pragma unroll
    for (int i=0;i<8;i++)
        #pragma unroll
        for (int j=0;j<8;j++) acc[i][j]=0.f;

    for (int k0 = 0; k0 < 256; k0 += 32) {
        #pragma unroll
        for (int it=0; it<4; it++) {
            int s = tid + it*256;           // 1024 float4 slots
            int row = s>>3, c4 = s&7;
            float4 v = *(const float4*)&x[(size_t)(m0+row)*256 + k0 + c4*4];
            As[c4*4+0][row]=v.x; As[c4*4+1][row]=v.y;
            As[c4*4+2][row]=v.z; As[c4*4+3][row]=v.w;
        }
        #pragma unroll
        for (int it=0; it<4; it++) {
            int s = tid + it*256;
            int kk = s>>5, c4 = s&31;
            *(float4*)&Bs[kk][c4*4] =
                *(const float4*)&Wg[(size_t)(k0+kk)*256 + j0p + c4*4];
        }
        __syncthreads();
        #pragma unroll
        for (int kk=0; kk<32; kk++) {
            float a[8], b[8];
            *(float4*)(a)   = *(const float4*)&As[kk][ty*8];
            *(float4*)(a+4) = *(const float4*)&As[kk][ty*8+4];
            *(float4*)(b)   = *(const float4*)&Bs[kk][tx*8];
            *(float4*)(b+4) = *(const float4*)&Bs[kk][tx*8+4];
            #pragma unroll
            for (int i=0;i<8;i++)
                #pragma unroll
                for (int j=0;j<8;j++) acc[i][j] = fmaf(a[i], b[j], acc[i][j]);
        }
        __syncthreads();
    }

    float bias[8];
    *(float4*)(bias)   = *(const float4*)&bg[j0p + tx*8];
    *(float4*)(bias+4) = *(const float4*)&bg[j0p + tx*8 + 4];
    #pragma unroll
    for (int i=0;i<8;i++) {
        size_t row = (size_t)(m0 + ty*8 + i);
        #pragma unroll
        for (int jq=0;jq<2;jq++) {
            float4 v;
            v.x = acc[i][jq*4+0] + bias[jq*4+0];
            v.y = acc[i][jq*4+1] + bias[jq*4+1];
            v.z = acc[i][jq*4+2] + bias[jq*4+2];
            v.w = acc[i][jq*4+3] + bias[jq*4+3];
            *(float4*)&g_xg[row*GG + n0 + tx*8 + jq*4] = v;
        }
    }
}

// ---------------------------------------------------------------------------
// Kernel 2: persistent clustered recurrence.
// 128 CTAs = 16 clusters x 8. Cluster owns 2 batches; CTA rank r owns h-cols
// [32r,32r+32) -> 128 U columns (4 gates x 32) resident in smem (128 KB).
// h exchanged via DSMEM, double-buffered by parity, 1 cluster.sync/step.
// smem floats: U_s 32768 | ps 2048 | z_s 256 | h_in 1024 = 36096 (144384 B)
// ---------------------------------------------------------------------------
#define REC_SMEM_BYTES (36096 * 4)

__global__ __launch_bounds__(256, 1) __cluster_dims__(8, 1, 1)
void lstm_rec_kernel(const float* __restrict__ Uf, const float* __restrict__ Ui,
                     const float* __restrict__ Uc, const float* __restrict__ Uo,
                     float* __restrict__ out, int write_state)
{
    extern __shared__ float sm[];
    float* U_s  = sm;                 // [k 0..255][col 0..127]
    float* ps   = sm + 32768;         // partials [8 warp][256 out]
    float* z_s  = ps + 2048;          // activated z [2 b][128 col]
    float* h_in = z_s + 256;          // [2 parity][2 b][256 h]

    const int tid  = threadIdx.x;
    const int w    = tid >> 5, lane = tid & 31;
    const int rank = blockIdx.x & 7;
    const int cid  = blockIdx.x >> 3;
    const int j0   = rank * 32;

    // Load U slice: col = gate*32 + jj  -> Ug[k][j0+jj]
    for (int s = tid; s < 8192; s += 256) {     // float4 slots
        int k = s >> 5, c4 = s & 31;
        int gate = c4 >> 3, jj = (c4 & 7) * 4;
        const float* Up = (gate==0)?Uf:(gate==1)?Ui:(gate==2)?Uc:Uo;
        *(float4*)&U_s[k*128 + c4*4] = *(const float4*)&Up[(size_t)k*256 + j0 + jj];
    }
    for (int s = tid; s < 1024; s += 256) h_in[s] = 0.f;
    __syncthreads();
    asm volatile("barrier.cluster.arrive.aligned;" ::: "memory");
    asm volatile("barrier.cluster.wait.aligned;"   ::: "memory");

    // reduction mapping: thread tid -> output o = tid = b*128 + col
    const int rb    = tid >> 7;
    const int rcol  = tid & 127;
    const int rgate = rcol >> 5;
    const size_t xg_base =
        (size_t)(cid*2 + rb) * SS * GG + (size_t)rgate*256 + j0 + (rcol & 31);

    // epilogue mapping (tid < 64): (batch eb, h-col j0+ej)
    const int eb = (tid >> 5) & 1;
    const int ej = tid & 31;
    float c_reg = 0.f;
    float* hid_ptr = out + (size_t)(cid*2 + eb)*SS*HH + j0 + ej;

    uint32_t la0, la1;   // local smem addrs of h_in[parity][eb][j0+ej]
    {
        float* p0 = h_in + eb*256 + j0 + ej;
        float* p1 = p0 + 512;
        asm("{ .reg .u64 t; cvta.to.shared.u64 t, %1; cvt.u32.u64 %0, t; }"
            : "=r"(la0) : "l"(p0));
        asm("{ .reg .u64 t; cvta.to.shared.u64 t, %1; cvt.u32.u64 %0, t; }"
            : "=r"(la1) : "l"(p1));
    }

    const float* Up0 = U_s + (w*32)*128 + lane*4;

    for (int t = 0; t < SS; t++) {
        // prefetch xg operand (consumed ~1000 cycles later)
        float xg_v = g_xg[xg_base + (size_t)t * GG];

        // preload this warp's 32-k h slice, both batches (broadcast LDS)
        const float* hb = h_in + (t & 1) * 512;
        float hA[32], hB[32];
        #pragma unroll
        for (int m = 0; m < 8; m++) {
            float4 v0 = *(const float4*)(hb + w*32 + m*4);
            hA[4*m]=v0.x; hA[4*m+1]=v0.y; hA[4*m+2]=v0.z; hA[4*m+3]=v0.w;
            float4 v1 = *(const float4*)(hb + 256 + w*32 + m*4);
            hB[4*m]=v1.x; hB[4*m+1]=v1.y; hB[4*m+2]=v1.z; hB[4*m+3]=v1.w;
        }

        // GEMV partials: 4 cols (float4) x 2 batches x 32 k = 256 FMA/thread
        float4 aA = make_float4(0.f,0.f,0.f,0.f);
        float4 aB = make_float4(0.f,0.f,0.f,0.f);
        #pragma unroll
        for (int k = 0; k < 32; k++) {
            float4 u = *(const float4*)(Up0 + k*128);
            float ha = hA[k], hb2 = hB[k];
            aA.x = fmaf(ha, u.x, aA.x);  aA.y = fmaf(ha, u.y, aA.y);
            aA.z = fmaf(ha, u.z, aA.z);  aA.w = fmaf(ha, u.w, aA.w);
            aB.x = fmaf(hb2, u.x, aB.x); aB.y = fmaf(hb2, u.y, aB.y);
            aB.z = fmaf(hb2, u.z, aB.z); aB.w = fmaf(hb2, u.w, aB.w);
        }
        *(float4*)&ps[w*256 + lane*4]       = aA;
        *(float4*)&ps[w*256 + 128 + lane*4] = aB;
        __syncthreads();

        // cross-warp reduce + bias'd xg + activation
        float z = xg_v;
        #pragma unroll
        for (int ww = 0; ww < 8; ww++) z += ps[ww*256 + tid];
        z_s[tid] = (rgate == 2) ? tanhf(z) : 1.f / (1.f + expf(-z));
        __syncthreads();

        // epilogue: 64 threads own (batch, h-col)
        if (tid < 64) {
            const float* zb = z_s + eb*128;
            float f  = zb[ej];
            float ii = zb[32 + ej];
            float g  = zb[64 + ej];
            float oo = zb[96 + ej];
            c_reg = f * c_reg + ii * g;
            float h = oo * tanhf(c_reg);
            hid_ptr[(size_t)t * HH] = h;

            // broadcast h to all 8 CTAs' h_in[(t+1)&1]
            uint32_t la = (t & 1) ? la0 : la1;
            #pragma unroll
            for (int r = 0; r < 8; r++) {
                uint32_t ra;
                asm volatile("mapa.shared::cluster.u32 %0, %1, %2;"
                             : "=r"(ra) : "r"(la), "r"(r));
                asm volatile("st.shared::cluster.f32 [%0], %1;"
                             :: "r"(ra), "f"(h) : "memory");
            }
            if (write_state && t == SS - 1) {
                size_t bidx = (size_t)(cid*2 + eb)*HH + j0 + ej;
                out[BSH + bidx] = h;                       // h_t
                out[BSH + (size_t)BB*HH + bidx] = c_reg;   // c_t
            }
        }
        asm volatile("barrier.cluster.arrive.aligned;" ::: "memory");
        asm volatile("barrier.cluster.wait.aligned;"   ::: "memory");
    }
}

// ---------------------------------------------------------------------------
extern "C" void kernel_launch(void* const* d_in, const int* in_sizes, int n_in,
                              void* d_out, int out_size)
{
    // order: x, W_f,U_f,b_f, W_i,U_i,b_i, W_o,U_o,b_o, W_c,U_c,b_c
    const float* x  = (const float*)d_in[0];
    const float* Wf = (const float*)d_in[1];
    const float* Uf = (const float*)d_in[2];
    const float* bf = (const float*)d_in[3];
    const float* Wi = (const float*)d_in[4];
    const float* Ui = (const float*)d_in[5];
    const float* bi = (const float*)d_in[6];
    const float* Wo = (const float*)d_in[7];
    const float* Uo = (const float*)d_in[8];
    const float* bo = (const float*)d_in[9];
    const float* Wc = (const float*)d_in[10];
    const float* Uc = (const float*)d_in[11];
    const float* bc = (const float*)d_in[12];
    float* out = (float*)d_out;

    static int smem_set = 0;
    if (!smem_set) {
        cudaFuncSetAttribute(lstm_rec_kernel,
                             cudaFuncAttributeMaxDynamicSharedMemorySize,
                             REC_SMEM_BYTES);
        smem_set = 1;
    }

    int write_state = ((size_t)out_size >= BSH + (size_t)2*BB*HH) ? 1 : 0;

    xg_gemm_kernel<<<4096, 256>>>(x, Wf, Wi, Wc, Wo, bf, bi, bc, bo);
    lstm_rec_kernel<<<128, 256, REC_SMEM_BYTES>>>(Uf, Ui, Uc, Uo, out, write_state);
}

// round 5
// speedup vs baseline: 1.0435x; 1.0435x over previous
#include <cuda_runtime.h>
#include <cstdint>
#include <math.h>

#define BB 32
#define SS 2048
#define HH 256
#define GG 1024                       // 4*H
#define BSH ((size_t)BB*SS*HH)        // hidden_seq elements

// 256 MB scratch: xg[B][S][4H], gate order f,i,c,o
__device__ float g_xg[(size_t)BB * SS * GG];

// ---------------------------------------------------------------------------
// Kernel 1: xg = x @ [Wf|Wi|Wc|Wo] + bias.  M=65536,K=256,N=1024.
// 128x128 CTA tile, 256 threads, 8x8 microtile.  (unchanged — known good)
// ---------------------------------------------------------------------------
__global__ __launch_bounds__(256) void xg_gemm_kernel(
    const float* __restrict__ x,
    const float* __restrict__ Wf, const float* __restrict__ Wi,
    const float* __restrict__ Wc, const float* __restrict__ Wo,
    const float* __restrict__ bf, const float* __restrict__ bi,
    const float* __restrict__ bc, const float* __restrict__ bo)
{
    __shared__ float As[32][132];     // A^T tile [k][m]
    __shared__ float Bs[32][128];     // B tile [k][n]

    const int nt = blockIdx.x & 7;
    const int m0 = (blockIdx.x >> 3) * 128;
    const int n0 = nt * 128;
    const int gate = n0 >> 8;         // tile fully inside one gate
    const float* Wg = (gate==0)?Wf:(gate==1)?Wi:(gate==2)?Wc:Wo;
    const float* bg = (gate==0)?bf:(gate==1)?bi:(gate==2)?bc:bo;
    const int j0p = n0 & 255;

    const int tid = threadIdx.x;
    const int tx = tid & 15, ty = tid >> 4;

    float acc[8][8];
    #pragma unroll
    for (int i=0;i<8;i++)
        #pragma unroll
        for (int j=0;j<8;j++) acc[i][j]=0.f;

    for (int k0 = 0; k0 < 256; k0 += 32) {
        #pragma unroll
        for (int it=0; it<4; it++) {
            int s = tid + it*256;           // 1024 float4 slots
            int row = s>>3, c4 = s&7;
            float4 v = *(const float4*)&x[(size_t)(m0+row)*256 + k0 + c4*4];
            As[c4*4+0][row]=v.x; As[c4*4+1][row]=v.y;
            As[c4*4+2][row]=v.z; As[c4*4+3][row]=v.w;
        }
        #pragma unroll
        for (int it=0; it<4; it++) {
            int s = tid + it*256;
            int kk = s>>5, c4 = s&31;
            *(float4*)&Bs[kk][c4*4] =
                *(const float4*)&Wg[(size_t)(k0+kk)*256 + j0p + c4*4];
        }
        __syncthreads();
        #pragma unroll
        for (int kk=0; kk<32; kk++) {
            float a[8], b[8];
            *(float4*)(a)   = *(const float4*)&As[kk][ty*8];
            *(float4*)(a+4) = *(const float4*)&As[kk][ty*8+4];
            *(float4*)(b)   = *(const float4*)&Bs[kk][tx*8];
            *(float4*)(b+4) = *(const float4*)&Bs[kk][tx*8+4];
            #pragma unroll
            for (int i=0;i<8;i++)
                #pragma unroll
                for (int j=0;j<8;j++) acc[i][j] = fmaf(a[i], b[j], acc[i][j]);
        }
        __syncthreads();
    }

    float bias[8];
    *(float4*)(bias)   = *(const float4*)&bg[j0p + tx*8];
    *(float4*)(bias+4) = *(const float4*)&bg[j0p + tx*8 + 4];
    #pragma unroll
    for (int i=0;i<8;i++) {
        size_t row = (size_t)(m0 + ty*8 + i);
        #pragma unroll
        for (int jq=0;jq<2;jq++) {
            float4 v;
            v.x = acc[i][jq*4+0] + bias[jq*4+0];
            v.y = acc[i][jq*4+1] + bias[jq*4+1];
            v.z = acc[i][jq*4+2] + bias[jq*4+2];
            v.w = acc[i][jq*4+3] + bias[jq*4+3];
            *(float4*)&g_xg[row*GG + n0 + tx*8 + jq*4] = v;
        }
    }
}

// ---------------------------------------------------------------------------
// f32x2 packed-FMA helpers
// ---------------------------------------------------------------------------
__device__ __forceinline__ void ffma2(unsigned long long& d,
                                      unsigned long long a,
                                      unsigned long long b) {
    asm("fma.rn.f32x2 %0, %1, %2, %0;" : "+l"(d) : "l"(a), "l"(b));
}
__device__ __forceinline__ unsigned long long dup2(float h) {
    unsigned long long p;
    asm("mov.b64 %0, {%1, %1};" : "=l"(p) : "f"(h));
    return p;
}
__device__ __forceinline__ float2 unpack2(unsigned long long d) {
    float2 r;
    asm("mov.b64 {%0, %1}, %2;" : "=f"(r.x), "=f"(r.y) : "l"(d));
    return r;
}

// ---------------------------------------------------------------------------
// Kernel 2: persistent clustered recurrence.  512 threads/CTA, f32x2 math.
// 128 CTAs = 16 clusters x 8. Cluster owns 2 batches; CTA rank r owns h-cols
// [32r,32r+32) -> 128 U columns (4 gates x 32) resident in smem (128 KB).
// Each of the 16 warps handles a 16-k slice across all 128 cols x 2 batches.
// h exchanged via DSMEM, double-buffered by step parity, 1 cluster.sync/step.
// smem floats: U_s 32768 | ps 4096 | z_s 256 | h_buf 1024 = 38144 (152576 B)
// ---------------------------------------------------------------------------
#define REC_SMEM_BYTES (38144 * 4)

__global__ __launch_bounds__(512, 1) __cluster_dims__(8, 1, 1)
void lstm_rec_kernel(const float* __restrict__ Uf, const float* __restrict__ Ui,
                     const float* __restrict__ Uc, const float* __restrict__ Uo,
                     float* __restrict__ out, int write_state)
{
    extern __shared__ float sm[];
    float* U_s   = sm;                 // [k 0..255][col 0..127]
    float* ps    = sm + 32768;         // partials [16 warp][2 b][128 col]
    float* z_s   = ps + 4096;          // activated z [2 b][128 col]
    float* h_buf = z_s + 256;          // [2 parity][2 b][256 h]

    const int tid  = threadIdx.x;
    const int w    = tid >> 5, lane = tid & 31;
    const int rank = blockIdx.x & 7;
    const int cid  = blockIdx.x >> 3;
    const int j0   = rank * 32;

    // Load U slice: col = gate*32 + jj  -> Ug[k][j0+jj]
    for (int s = tid; s < 8192; s += 512) {     // float4 slots
        int k = s >> 5, c4 = s & 31;
        int gate = c4 >> 3, jj = (c4 & 7) * 4;
        const float* Up = (gate==0)?Uf:(gate==1)?Ui:(gate==2)?Uc:Uo;
        *(float4*)&U_s[k*128 + c4*4] = *(const float4*)&Up[(size_t)k*256 + j0 + jj];
    }
    for (int s = tid; s < 1024; s += 512) h_buf[s] = 0.f;
    __syncthreads();
    asm volatile("barrier.cluster.arrive.aligned;" ::: "memory");
    asm volatile("barrier.cluster.wait.aligned;"   ::: "memory");

    // reduce/activation mapping (tid < 256): o = tid = b*128 + col
    const int rb    = tid >> 7;
    const int rcol  = tid & 127;
    const int rgate = rcol >> 5;
    const size_t xg_base =
        (size_t)(cid*2 + rb) * SS * GG + (size_t)rgate*256 + j0 + (rcol & 31);

    // epilogue mapping (tid < 64): (batch eb, h-col j0+ej)
    const int eb = (tid >> 5) & 1;
    const int ej = tid & 31;
    float c_reg = 0.f;
    float* hid_ptr = out + (size_t)(cid*2 + eb)*SS*HH + j0 + ej;

    uint32_t la0, la1;   // local smem addrs of h_buf[parity][eb][j0+ej]
    {
        float* p0 = h_buf + eb*256 + j0 + ej;
        float* p1 = p0 + 512;
        asm("{ .reg .u64 t; cvta.to.shared.u64 t, %1; cvt.u32.u64 %0, t; }"
            : "=r"(la0) : "l"(p0));
        asm("{ .reg .u64 t; cvta.to.shared.u64 t, %1; cvt.u32.u64 %0, t; }"
            : "=r"(la1) : "l"(p1));
    }

    // this warp's U base: k-slice [w*16, w*16+16), 4 cols at lane*4
    const float* Up0 = U_s + (w*16)*128 + lane*4;
    float* psA = ps + w*256 + lane*4;         // [w][b=0][col]
    float* psB = psA + 128;                   // [w][b=1][col]

    for (int t = 0; t < SS; t++) {
        // prefetch xg operand (consumed after the GEMV)
        float xg_v = (tid < 256) ? g_xg[xg_base + (size_t)t * GG] : 0.f;

        // load this warp's 16-k h slice, both batches (broadcast LDS)
        const float* hb = h_buf + (t & 1) * 512;
        float hA[16], hB[16];
        #pragma unroll
        for (int m = 0; m < 4; m++) {
            float4 v0 = *(const float4*)(hb + w*16 + m*4);
            hA[4*m]=v0.x; hA[4*m+1]=v0.y; hA[4*m+2]=v0.z; hA[4*m+3]=v0.w;
            float4 v1 = *(const float4*)(hb + 256 + w*16 + m*4);
            hB[4*m]=v1.x; hB[4*m+1]=v1.y; hB[4*m+2]=v1.z; hB[4*m+3]=v1.w;
        }

        // GEMV partials: 4 cols x 2 batches x 16 k, f32x2 over column pairs
        unsigned long long aA01=0ull, aA23=0ull, aB01=0ull, aB23=0ull;
        #pragma unroll
        for (int k = 0; k < 16; k++) {
            double2 ud = *(const double2*)(Up0 + k*128);   // (u0,u1),(u2,u3)
            unsigned long long u01 = __double_as_longlong(ud.x);
            unsigned long long u23 = __double_as_longlong(ud.y);
            unsigned long long ha2 = dup2(hA[k]);
            unsigned long long hb2 = dup2(hB[k]);
            ffma2(aA01, ha2, u01);
            ffma2(aA23, ha2, u23);
            ffma2(aB01, hb2, u01);
            ffma2(aB23, hb2, u23);
        }
        {
            float2 a01 = unpack2(aA01), a23 = unpack2(aA23);
            float2 b01 = unpack2(aB01), b23 = unpack2(aB23);
            *(float4*)psA = make_float4(a01.x, a01.y, a23.x, a23.y);
            *(float4*)psB = make_float4(b01.x, b01.y, b23.x, b23.y);
        }
        __syncthreads();

        // cross-warp reduce + xg + activation (256 threads)
        if (tid < 256) {
            float z = xg_v;
            #pragma unroll
            for (int ww = 0; ww < 16; ww++) z += ps[ww*256 + tid];
            z_s[tid] = (rgate == 2) ? tanhf(z) : 1.f / (1.f + expf(-z));
        }
        __syncthreads();

        // epilogue: 64 threads own (batch, h-col)
        if (tid < 64) {
            const float* zb = z_s + eb*128;
            float f  = zb[ej];
            float ii = zb[32 + ej];
            float g  = zb[64 + ej];
            float oo = zb[96 + ej];
            c_reg = f * c_reg + ii * g;
            float h = oo * tanhf(c_reg);
            hid_ptr[(size_t)t * HH] = h;

            // broadcast h to all 8 CTAs' h_buf[(t+1)&1]
            uint32_t la = (t & 1) ? la0 : la1;
            #pragma unroll
            for (int r = 0; r < 8; r++) {
                uint32_t ra;
                asm volatile("mapa.shared::cluster.u32 %0, %1, %2;"
                             : "=r"(ra) : "r"(la), "r"(r));
                asm volatile("st.shared::cluster.f32 [%0], %1;"
                             :: "r"(ra), "f"(h) : "memory");
            }
            if (write_state && t == SS - 1) {
                size_t bidx = (size_t)(cid*2 + eb)*HH + j0 + ej;
                out[BSH + bidx] = h;                       // h_t
                out[BSH + (size_t)BB*HH + bidx] = c_reg;   // c_t
            }
        }
        asm volatile("barrier.cluster.arrive.aligned;" ::: "memory");
        asm volatile("barrier.cluster.wait.aligned;"   ::: "memory");
    }
}

// ---------------------------------------------------------------------------
extern "C" void kernel_launch(void* const* d_in, const int* in_sizes, int n_in,
                              void* d_out, int out_size)
{
    // order: x, W_f,U_f,b_f, W_i,U_i,b_i, W_o,U_o,b_o, W_c,U_c,b_c
    const float* x  = (const float*)d_in[0];
    const float* Wf = (const float*)d_in[1];
    const float* Uf = (const float*)d_in[2];
    const float* bf = (const float*)d_in[3];
    const float* Wi = (const float*)d_in[4];
    const float* Ui = (const float*)d_in[5];
    const float* bi = (const float*)d_in[6];
    const float* Wo = (const float*)d_in[7];
    const float* Uo = (const float*)d_in[8];
    const float* bo = (const float*)d_in[9];
    const float* Wc = (const float*)d_in[10];
    const float* Uc = (const float*)d_in[11];
    const float* bc = (const float*)d_in[12];
    float* out = (float*)d_out;

    static int smem_set = 0;
    if (!smem_set) {
        cudaFuncSetAttribute(lstm_rec_kernel,
                             cudaFuncAttributeMaxDynamicSharedMemorySize,
                             REC_SMEM_BYTES);
        smem_set = 1;
    }

    int write_state = ((size_t)out_size >= BSH + (size_t)2*BB*HH) ? 1 : 0;

    xg_gemm_kernel<<<4096, 256>>>(x, Wf, Wi, Wc, Wo, bf, bi, bc, bo);
    lstm_rec_kernel<<<128, 512, REC_SMEM_BYTES>>>(Uf, Ui, Uc, Uo, out, write_state);
}

// round 6
// speedup vs baseline: 1.4566x; 1.3959x over previous
#include <cuda_runtime.h>
#include <cstdint>
#include <math.h>

#define BB 32
#define SS 2048
#define HH 256
#define GG 1024                       // 4*H
#define BSH ((size_t)BB*SS*HH)        // hidden_seq elements

// 256 MB scratch: xg[B][S][4H], gate order f,i,c,o
__device__ float g_xg[(size_t)BB * SS * GG];

// ---------------------------------------------------------------------------
// Kernel 1: xg = x @ [Wf|Wi|Wc|Wo] + bias.  M=65536,K=256,N=1024. (unchanged)
// ---------------------------------------------------------------------------
__global__ __launch_bounds__(256) void xg_gemm_kernel(
    const float* __restrict__ x,
    const float* __restrict__ Wf, const float* __restrict__ Wi,
    const float* __restrict__ Wc, const float* __restrict__ Wo,
    const float* __restrict__ bf, const float* __restrict__ bi,
    const float* __restrict__ bc, const float* __restrict__ bo)
{
    __shared__ float As[32][132];
    __shared__ float Bs[32][128];

    const int nt = blockIdx.x & 7;
    const int m0 = (blockIdx.x >> 3) * 128;
    const int n0 = nt * 128;
    const int gate = n0 >> 8;
    const float* Wg = (gate==0)?Wf:(gate==1)?Wi:(gate==2)?Wc:Wo;
    const float* bg = (gate==0)?bf:(gate==1)?bi:(gate==2)?bc:bo;
    const int j0p = n0 & 255;

    const int tid = threadIdx.x;
    const int tx = tid & 15, ty = tid >> 4;

    float acc[8][8];
    #pragma unroll
    for (int i=0;i<8;i++)
        #pragma unroll
        for (int j=0;j<8;j++) acc[i][j]=0.f;

    for (int k0 = 0; k0 < 256; k0 += 32) {
        #pragma unroll
        for (int it=0; it<4; it++) {
            int s = tid + it*256;
            int row = s>>3, c4 = s&7;
            float4 v = *(const float4*)&x[(size_t)(m0+row)*256 + k0 + c4*4];
            As[c4*4+0][row]=v.x; As[c4*4+1][row]=v.y;
            As[c4*4+2][row]=v.z; As[c4*4+3][row]=v.w;
        }
        #pragma unroll
        for (int it=0; it<4; it++) {
            int s = tid + it*256;
            int kk = s>>5, c4 = s&31;
            *(float4*)&Bs[kk][c4*4] =
                *(const float4*)&Wg[(size_t)(k0+kk)*256 + j0p + c4*4];
        }
        __syncthreads();
        #pragma unroll
        for (int kk=0; kk<32; kk++) {
            float a[8], b[8];
            *(float4*)(a)   = *(const float4*)&As[kk][ty*8];
            *(float4*)(a+4) = *(const float4*)&As[kk][ty*8+4];
            *(float4*)(b)   = *(const float4*)&Bs[kk][tx*8];
            *(float4*)(b+4) = *(const float4*)&Bs[kk][tx*8+4];
            #pragma unroll
            for (int i=0;i<8;i++)
                #pragma unroll
                for (int j=0;j<8;j++) acc[i][j] = fmaf(a[i], b[j], acc[i][j]);
        }
        __syncthreads();
    }

    float bias[8];
    *(float4*)(bias)   = *(const float4*)&bg[j0p + tx*8];
    *(float4*)(bias+4) = *(const float4*)&bg[j0p + tx*8 + 4];
    #pragma unroll
    for (int i=0;i<8;i++) {
        size_t row = (size_t)(m0 + ty*8 + i);
        #pragma unroll
        for (int jq=0;jq<2;jq++) {
            float4 v;
            v.x = acc[i][jq*4+0] + bias[jq*4+0];
            v.y = acc[i][jq*4+1] + bias[jq*4+1];
            v.z = acc[i][jq*4+2] + bias[jq*4+2];
            v.w = acc[i][jq*4+3] + bias[jq*4+3];
            *(float4*)&g_xg[row*GG + n0 + tx*8 + jq*4] = v;
        }
    }
}

// ---------------------------------------------------------------------------
// helpers
// ---------------------------------------------------------------------------
__device__ __forceinline__ void ffma2(unsigned long long& d,
                                      unsigned long long a,
                                      unsigned long long b) {
    asm("fma.rn.f32x2 %0, %1, %2, %0;" : "+l"(d) : "l"(a), "l"(b));
}
__device__ __forceinline__ unsigned long long dup2(float h) {
    unsigned long long p;
    asm("mov.b64 %0, {%1, %1};" : "=l"(p) : "f"(h));
    return p;
}
__device__ __forceinline__ float2 unpack2(unsigned long long d) {
    float2 r;
    asm("mov.b64 {%0, %1}, %2;" : "=f"(r.x), "=f"(r.y) : "l"(d));
    return r;
}
__device__ __forceinline__ uint32_t smem_u32(const void* p) {
    uint32_t a;
    asm("{ .reg .u64 t; cvta.to.shared.u64 t, %1; cvt.u32.u64 %0, t; }"
        : "=r"(a) : "l"(p));
    return a;
}
__device__ __forceinline__ float fast_sig(float z) {
    return __fdividef(1.f, 1.f + __expf(-z));
}
__device__ __forceinline__ float fast_tanh(float z) {
    return __fdividef(2.f, 1.f + __expf(-2.f * z)) - 1.f;
}
__device__ __forceinline__ void mbar_init(uint32_t mb, uint32_t cnt) {
    asm volatile("mbarrier.init.shared.b64 [%0], %1;" :: "r"(mb), "r"(cnt) : "memory");
}
__device__ __forceinline__ void mbar_expect_tx(uint32_t mb, uint32_t bytes) {
    asm volatile("mbarrier.arrive.expect_tx.shared.b64 _, [%0], %1;"
                 :: "r"(mb), "r"(bytes) : "memory");
}
__device__ __forceinline__ void mbar_wait(uint32_t mb, uint32_t parity) {
    uint32_t done;
    asm volatile(
        "{\n\t.reg .pred p;\n\t"
        "mbarrier.try_wait.parity.acquire.cta.shared::cta.b64 p, [%1], %2;\n\t"
        "selp.b32 %0, 1, 0, p;\n\t}"
        : "=r"(done) : "r"(mb), "r"(parity) : "memory");
    while (!done) {
        asm volatile(
            "{\n\t.reg .pred p;\n\t"
            "mbarrier.try_wait.parity.acquire.cta.shared::cta.b64 p, [%1], %2, 0x989680;\n\t"
            "selp.b32 %0, 1, 0, p;\n\t}"
            : "=r"(done) : "r"(mb), "r"(parity) : "memory");
    }
}

// ---------------------------------------------------------------------------
// Kernel 2: persistent clustered recurrence, mbarrier/st.async handshake.
// 128 CTAs = 16 clusters x 8. CTA rank r owns h-cols [32r,32r+32) (128 U cols
// in smem). 16 warps each take a 16-k slice x 128 cols x 2 batches (f32x2).
// Per step: 1 __syncthreads + 1 local mbar wait. h broadcast via st.async
// with complete_tx into peers' h_buf[(t+1)&1], 2048 B expected per CTA.
// smem floats: mbar 4 | pad 12 | U_s 32768 | ps 4096 | h_buf 1024 = 37904
// ---------------------------------------------------------------------------
#define REC_SMEM_FLOATS 37904
#define REC_SMEM_BYTES (REC_SMEM_FLOATS * 4)

__global__ __launch_bounds__(512, 1) __cluster_dims__(8, 1, 1)
void lstm_rec_kernel(const float* __restrict__ Uf, const float* __restrict__ Ui,
                     const float* __restrict__ Uc, const float* __restrict__ Uo,
                     float* __restrict__ out, int write_state)
{
    extern __shared__ float sm[];
    float* U_s   = sm + 16;            // [k 0..255][col 0..127]
    float* ps    = U_s + 32768;        // partials [16 warp][2 b][128 col] (swizzled)
    float* h_buf = ps + 4096;          // [2 parity][2 b][256 h]

    const int tid  = threadIdx.x;
    const int w    = tid >> 5, lane = tid & 31;
    const int rank = blockIdx.x & 7;
    const int cid  = blockIdx.x >> 3;
    const int j0   = rank * 32;

    uint32_t mb_addr[2];
    mb_addr[0] = smem_u32(sm);
    mb_addr[1] = mb_addr[0] + 8;

    // Load U slice: col = gate*32 + jj  -> Ug[k][j0+jj]
    for (int s = tid; s < 8192; s += 512) {     // float4 slots
        int k = s >> 5, c4 = s & 31;
        int gate = c4 >> 3, jj = (c4 & 7) * 4;
        const float* Up = (gate==0)?Uf:(gate==1)?Ui:(gate==2)?Uc:Uo;
        *(float4*)&U_s[k*128 + c4*4] = *(const float4*)&Up[(size_t)k*256 + j0 + jj];
    }
    for (int s = tid; s < 1024; s += 512) h_buf[s] = 0.f;
    if (tid == 0) {
        mbar_init(mb_addr[0], 1);
        mbar_init(mb_addr[1], 1);
        mbar_expect_tx(mb_addr[0], 2048);
        mbar_expect_tx(mb_addr[1], 2048);
    }
    __syncthreads();
    asm volatile("barrier.cluster.arrive.aligned;" ::: "memory");
    asm volatile("barrier.cluster.wait.aligned;"   ::: "memory");

    // reduce/epilogue mapping (tid < 256): warp holds all 4 gates of 8 h-cols
    const int rb    = tid >> 7;          // batch
    const int lane8 = lane & 7;
    const int g     = lane >> 3;         // gate 0..3 (f,i,c,o)
    const int w4    = (tid >> 5) & 3;    // warp-within-batch
    const int jj    = w4 * 8 + lane8;    // h-col within rank slice (0..31)
    const size_t xg_base =
        (size_t)(cid*2 + rb) * SS * GG + (size_t)g*256 + j0 + jj;
    const int ridx  = rb*128 + g*32 + (jj ^ (g << 3));   // swizzled partial idx

    float c_reg = 0.f;
    float* hid_ptr = out + (size_t)(cid*2 + rb)*SS*HH + j0 + jj;

    uint32_t la_par[2];  // local addr of h_buf[q][rb][j0+jj]
    la_par[0] = smem_u32(h_buf + rb*256 + j0 + jj);
    la_par[1] = la_par[0] + 512*4;

    // GEMV: warp k-slice [w*16,+16), lane covers 4 cols x 2 batches
    const float* Up0 = U_s + (w*16)*128 + lane*4;
    float* psA = ps + w*256 + ((lane*4) ^ (lane & 24));  // XOR-swizzled
    float* psB = psA + 128;

    int ph0 = 0, ph1 = 0;

    for (int t = 0; t < SS; t++) {
        // xg load issued BEFORE the wait (independent of h -> hidden)
        float xg_v = 0.f;
        if (tid < 256) xg_v = g_xg[xg_base + (size_t)t * GG];

        if (t > 0) {
            if (t & 1) { mbar_wait(mb_addr[1], ph1); ph1 ^= 1; }
            else       { mbar_wait(mb_addr[0], ph0); ph0 ^= 1; }
            if (tid == 0) mbar_expect_tx(mb_addr[t & 1], 2048);
        }

        // h preload (this warp's 16-k slice, both batches)
        const float* hb = h_buf + (t & 1) * 512;
        float hA[16], hB[16];
        #pragma unroll
        for (int m = 0; m < 4; m++) {
            float4 v0 = *(const float4*)(hb + w*16 + m*4);
            hA[4*m]=v0.x; hA[4*m+1]=v0.y; hA[4*m+2]=v0.z; hA[4*m+3]=v0.w;
            float4 v1 = *(const float4*)(hb + 256 + w*16 + m*4);
            hB[4*m]=v1.x; hB[4*m+1]=v1.y; hB[4*m+2]=v1.z; hB[4*m+3]=v1.w;
        }

        // GEMV partials (f32x2 over column pairs)
        unsigned long long aA01=0ull, aA23=0ull, aB01=0ull, aB23=0ull;
        #pragma unroll
        for (int k = 0; k < 16; k++) {
            double2 ud = *(const double2*)(Up0 + k*128);
            unsigned long long u01 = __double_as_longlong(ud.x);
            unsigned long long u23 = __double_as_longlong(ud.y);
            unsigned long long ha2 = dup2(hA[k]);
            unsigned long long hb2 = dup2(hB[k]);
            ffma2(aA01, ha2, u01);
            ffma2(aA23, ha2, u23);
            ffma2(aB01, hb2, u01);
            ffma2(aB23, hb2, u23);
        }
        {
            float2 a01 = unpack2(aA01), a23 = unpack2(aA23);
            float2 b01 = unpack2(aB01), b23 = unpack2(aB23);
            *(float4*)psA = make_float4(a01.x, a01.y, a23.x, a23.y);
            *(float4*)psB = make_float4(b01.x, b01.y, b23.x, b23.y);
        }
        __syncthreads();

        if (tid < 256) {
            // cross-warp reduce (conflict-free via XOR swizzle) + activation
            float z = xg_v;
            #pragma unroll
            for (int ww = 0; ww < 16; ww++) z += ps[ww*256 + ridx];
            z = (g == 2) ? fast_tanh(z) : fast_sig(z);

            // gather gates into g==0 lanes
            float zi = __shfl_sync(0xffffffffu, z, lane8 + 8);
            float zg = __shfl_sync(0xffffffffu, z, lane8 + 16);
            float zo = __shfl_sync(0xffffffffu, z, lane8 + 24);

            if (g == 0) {
                c_reg = z * c_reg + zi * zg;       // z is the f gate
                float h = zo * fast_tanh(c_reg);
                hid_ptr[(size_t)t * HH] = h;

                if (t < SS - 1) {
                    uint32_t la = la_par[(t + 1) & 1];
                    uint32_t mb = mb_addr[(t + 1) & 1];
                    #pragma unroll
                    for (int r = 0; r < 8; r++) {
                        uint32_t ra, rm;
                        asm volatile("mapa.shared::cluster.u32 %0, %1, %2;"
                                     : "=r"(ra) : "r"(la), "r"(r));
                        asm volatile("mapa.shared::cluster.u32 %0, %1, %2;"
                                     : "=r"(rm) : "r"(mb), "r"(r));
                        asm volatile(
                            "st.async.shared::cluster.mbarrier::complete_tx::bytes.f32 [%0], %1, [%2];"
                            :: "r"(ra), "f"(h), "r"(rm) : "memory");
                    }
                }
                if (write_state && t == SS - 1) {
                    size_t bidx = (size_t)(cid*2 + rb)*HH + j0 + jj;
                    out[BSH + bidx] = h;                       // h_t
                    out[BSH + (size_t)BB*HH + bidx] = c_reg;   // c_t
                }
            }
        }
    }

    // safe teardown
    asm volatile("barrier.cluster.arrive.aligned;" ::: "memory");
    asm volatile("barrier.cluster.wait.aligned;"   ::: "memory");
}

// ---------------------------------------------------------------------------
extern "C" void kernel_launch(void* const* d_in, const int* in_sizes, int n_in,
                              void* d_out, int out_size)
{
    // order: x, W_f,U_f,b_f, W_i,U_i,b_i, W_o,U_o,b_o, W_c,U_c,b_c
    const float* x  = (const float*)d_in[0];
    const float* Wf = (const float*)d_in[1];
    const float* Uf = (const float*)d_in[2];
    const float* bf = (const float*)d_in[3];
    const float* Wi = (const float*)d_in[4];
    const float* Ui = (const float*)d_in[5];
    const float* bi = (const float*)d_in[6];
    const float* Wo = (const float*)d_in[7];
    const float* Uo = (const float*)d_in[8];
    const float* bo = (const float*)d_in[9];
    const float* Wc = (const float*)d_in[10];
    const float* Uc = (const float*)d_in[11];
    const float* bc = (const float*)d_in[12];
    float* out = (float*)d_out;

    static int smem_set = 0;
    if (!smem_set) {
        cudaFuncSetAttribute(lstm_rec_kernel,
                             cudaFuncAttributeMaxDynamicSharedMemorySize,
                             REC_SMEM_BYTES);
        smem_set = 1;
    }

    int write_state = ((size_t)out_size >= BSH + (size_t)2*BB*HH) ? 1 : 0;

    xg_gemm_kernel<<<4096, 256>>>(x, Wf, Wi, Wc, Wo, bf, bi, bc, bo);
    lstm_rec_kernel<<<128, 512, REC_SMEM_BYTES>>>(Uf, Ui, Uc, Uo, out, write_state);
}